// round 12
// baseline (speedup 1.0000x reference)
#include <cuda_runtime.h>
#include <cuda_fp16.h>
#include <cstdint>
#include <math.h>

#define BATCH_ 4096
#define HID_   2048
#define KTOT   4096            // K = INPUT(2048 from x) ++ HIDDEN(2048 from h)
#define BH     ((size_t)BATCH_ * HID_)

// GEMM tiling: CTA = 128(m) x 64(n) x 4 gates  (256 B-rows staged)
#define BM 128
#define BN 64
#define BK 32
#define STAGES 4
#define NKC (KTOT / BK)        // 128 k-iterations

// SMEM stage layout (40KB per stage, 4 stages = 160KB)
#define OFF_A   0
#define OFF_BHI 8192
#define OFF_BLO 24576
#define ST_BYTES 40960
#define SMEM_TOTAL (STAGES * ST_BYTES)

// Epilogue exchange layout (reuses the same dynamic smem after the mainloop)
#define EPS_STRIDE 265                   // floats per m-row (odd mod 32 -> conflict-free)
#define BIAS_OFF   (128 * EPS_STRIDE)    // 256 bias floats after the tile

// ---------------- scratch (device globals; allocation-free) ----------------
__device__ __half g_A[(size_t)BATCH_ * KTOT];          // [b][k] f16      32MB
__device__ __half g_B_hi[(size_t)4 * HID_ * KTOT];     // [g*2048+n][k]   64MB
__device__ __half g_B_lo[(size_t)4 * HID_ * KTOT];     // f16 residual    64MB

// ---------------- PTX helpers (base ISA only) ----------------
__device__ __forceinline__ uint32_t smem_u32(const void* p) {
    uint32_t a;
    asm("{ .reg .u64 t; cvta.to.shared.u64 t, %1; cvt.u32.u64 %0, t; }" : "=r"(a) : "l"(p));
    return a;
}
__device__ __forceinline__ void cp16(uint32_t dst, const void* src) {
    asm volatile("cp.async.cg.shared.global [%0], [%1], 16;" :: "r"(dst), "l"(src));
}
__device__ __forceinline__ void cp_commit() { asm volatile("cp.async.commit_group;" ::: "memory"); }
template <int N>
__device__ __forceinline__ void cp_wait() { asm volatile("cp.async.wait_group %0;" :: "n"(N) : "memory"); }

__device__ __forceinline__ void ldsm4(uint32_t* r, uint32_t addr) {
    asm volatile("ldmatrix.sync.aligned.m8n8.x4.shared.b16 {%0,%1,%2,%3}, [%4];"
                 : "=r"(r[0]), "=r"(r[1]), "=r"(r[2]), "=r"(r[3]) : "r"(addr));
}
__device__ __forceinline__ void mma16816(float* d, const uint32_t* a, uint32_t b0, uint32_t b1) {
    asm volatile(
        "mma.sync.aligned.m16n8k16.row.col.f32.f16.f16.f32 "
        "{%0,%1,%2,%3}, {%4,%5,%6,%7}, {%8,%9}, {%0,%1,%2,%3};"
        : "+f"(d[0]), "+f"(d[1]), "+f"(d[2]), "+f"(d[3])
        : "r"(a[0]), "r"(a[1]), "r"(a[2]), "r"(a[3]), "r"(b0), "r"(b1));
}

// 64B-row swizzle: 16B-column index XORed with (row>>1)&3 -> conflict-free for
// cp.async 16B stores and ldmatrix 8-row groups.  (proven R10/R11)
__device__ __forceinline__ uint32_t sw64(int row, int k2) {
    return (uint32_t)(row * 64 + ((k2 ^ ((row >> 1) & 3)) << 4));
}

// ---------------- merged conversion kernel ----------------
// z==0          : A = f16(x | h), element-wise, 8192 logical blocks
// z in 1..4     : gate g=z-1, transpose+split weights -> Bt[g*2048+n][k] f16 hi/lo
__global__ __launch_bounds__(256) void conv_kernel(
    const float* __restrict__ x, const float* __restrict__ h,
    const float* __restrict__ w_ih, const float* __restrict__ w_hh)
{
    if (blockIdx.z == 0) {
        const int bid = blockIdx.y * 64 + blockIdx.x;        // 0..8191
        const size_t e = ((size_t)bid * 256 + threadIdx.x) * 4;  // < 4096*2048 exactly
        const int row = (int)(e >> 11);
        const int col = (int)(e & 2047);
        const float4 xv = *reinterpret_cast<const float4*>(x + e);
        const float4 hv = *reinterpret_cast<const float4*>(h + e);
        const size_t base = (size_t)row * KTOT + col;
        __half2* a0 = reinterpret_cast<__half2*>(g_A + base);
        __half2* a1 = reinterpret_cast<__half2*>(g_A + base + 2048);
        a0[0] = __floats2half2_rn(xv.x, xv.y);
        a0[1] = __floats2half2_rn(xv.z, xv.w);
        a1[0] = __floats2half2_rn(hv.x, hv.y);
        a1[1] = __floats2half2_rn(hv.z, hv.w);
    } else {
        __shared__ float t[32][33];
        const int g = blockIdx.z - 1;
        const int nt = blockIdx.x * 32;      // 64 blocks * 32 = 2048
        const int kt = blockIdx.y * 32;      // 128 blocks * 32 = 4096
        const int tx = threadIdx.x & 31;
        const int ty = threadIdx.x >> 5;     // 0..7
#pragma unroll
        for (int r = 0; r < 4; r++) {
            const int kk = kt + ty + r * 8;
            const float* src = (kk < 2048)
                ? (w_ih + ((size_t)g * 2048 + kk) * HID_)
                : (w_hh + ((size_t)g * 2048 + (kk - 2048)) * HID_);
            t[ty + r * 8][tx] = src[nt + tx];
        }
        __syncthreads();
#pragma unroll
        for (int r = 0; r < 4; r++) {
            const int nn = nt + ty + r * 8;
            const float v = t[tx][ty + r * 8];
            const __half hi = __float2half_rn(v);
            const __half lo = __float2half_rn(v - __half2float(hi));
            const size_t off = ((size_t)g * HID_ + nn) * KTOT + kt + tx;
            g_B_hi[off] = hi;
            g_B_lo[off] = lo;
        }
    }
}

// ---------------- fused f16 2-split GEMM + LSTM epilogue ----------------
__device__ __forceinline__ float sigmoid_f(float v) { return 1.0f / (1.0f + expf(-v)); }

__global__ __launch_bounds__(256, 1) void lstm_fused_kernel(
    const float* __restrict__ cprev, const float* __restrict__ b_ih,
    const float* __restrict__ b_hh, float* __restrict__ out)
{
    extern __shared__ char smem[];
    const uint32_t sb = smem_u32(smem);
    const int tid = threadIdx.x;
    const int wid = tid >> 5;
    const int lid = tid & 31;
    const int wr = wid >> 2;       // 0..1  (64-row m band)
    const int wc = wid & 3;        // 0..3  == GATE index (64-col band of the 256 B rows)
    const int m0 = blockIdx.x * BM;
    const int n0 = blockIdx.y * BN;

    // ---- producer per-thread constants ----
    // A: 128 rows x 32k f16 (512 x 16B); 2 chunks/thread
    size_t gA[2]; uint32_t oA[2];
    // B: 256 rows x 32k f16, hi+lo (1024 x 16B each); 4 chunks/thread each
    size_t gB[4]; uint32_t oB[4];
#pragma unroll
    for (int j = 0; j < 2; j++) {
        const int idx = tid + j * 256;
        const int r = idx >> 2, k2 = idx & 3;
        oA[j] = sw64(r, k2);
        gA[j] = (size_t)(m0 + r) * KTOT + k2 * 8;
    }
#pragma unroll
    for (int j = 0; j < 4; j++) {
        const int idx = tid + j * 256;
        const int r = idx >> 2, k2 = idx & 3;   // r 0..255: gate=r>>6, n=n0+(r&63)
        oB[j] = sw64(r, k2);
        gB[j] = ((size_t)(r >> 6) * HID_ + n0 + (r & 63)) * KTOT + k2 * 8;
    }

    // ---- consumer ldmatrix offsets (ko=0; ko=1 == ^32) ----
    const int lrow = lid & 15;
    const int lk2  = lid >> 4;
    uint32_t aOff[4], bOff[4];
#pragma unroll
    for (int i = 0; i < 4; i++)    aOff[i]  = sw64(wr * 64 + i * 16 + lrow, lk2);
#pragma unroll
    for (int nt = 0; nt < 4; nt++) bOff[nt] = sw64(wc * 64 + nt * 16 + lrow, lk2);

    float acc[4][8][4];
#pragma unroll
    for (int i = 0; i < 4; i++)
#pragma unroll
        for (int j = 0; j < 8; j++)
#pragma unroll
            for (int p = 0; p < 4; p++) acc[i][j][p] = 0.0f;

    auto load_stage = [&](int kt) {
        const uint32_t base = sb + (uint32_t)(kt & (STAGES - 1)) * ST_BYTES;
        const int k0 = kt * BK;
#pragma unroll
        for (int j = 0; j < 2; j++)
            cp16(base + OFF_A + oA[j], g_A + gA[j] + k0);
#pragma unroll
        for (int j = 0; j < 4; j++) {
            cp16(base + OFF_BHI + oB[j], g_B_hi + gB[j] + k0);
            cp16(base + OFF_BLO + oB[j], g_B_lo + gB[j] + k0);
        }
    };

#pragma unroll
    for (int kt = 0; kt < STAGES - 1; kt++) { load_stage(kt); cp_commit(); }

    for (int kt = 0; kt < NKC; kt++) {
        cp_wait<STAGES - 2>();
        __syncthreads();           // stage kt ready; WAR-guards refill of stage (kt+3)&3

        // issue next stage's loads first so DMA overlaps the whole MMA burst
        const int np = kt + STAGES - 1;
        if (np < NKC) load_stage(np);
        cp_commit();

        const uint32_t base = sb + (uint32_t)(kt & (STAGES - 1)) * ST_BYTES;

#pragma unroll
        for (int ko = 0; ko < 2; ko++) {           // two k16 steps per k32 stage
            const uint32_t x32 = ko ? 32u : 0u;
            uint32_t a[4][4], bhf[4][4], blf[4][4];
#pragma unroll
            for (int i = 0; i < 4; i++)
                ldsm4(a[i], base + OFF_A + (aOff[i] ^ x32));
#pragma unroll
            for (int nt = 0; nt < 4; nt++) {
                ldsm4(bhf[nt], base + OFF_BHI + (bOff[nt] ^ x32));
                ldsm4(blf[nt], base + OFF_BLO + (bOff[nt] ^ x32));
            }
            // pass 1: a * b_hi   (32 independent MMAs)
#pragma unroll
            for (int nt = 0; nt < 4; nt++)
#pragma unroll
                for (int i = 0; i < 4; i++) {
                    mma16816(acc[i][2 * nt],     a[i], bhf[nt][0], bhf[nt][2]);
                    mma16816(acc[i][2 * nt + 1], a[i], bhf[nt][1], bhf[nt][3]);
                }
            // pass 2: a * b_lo
#pragma unroll
            for (int nt = 0; nt < 4; nt++)
#pragma unroll
                for (int i = 0; i < 4; i++) {
                    mma16816(acc[i][2 * nt],     a[i], blf[nt][0], blf[nt][2]);
                    mma16816(acc[i][2 * nt + 1], a[i], blf[nt][1], blf[nt][3]);
                }
        }
    }

    // ---------------- fused epilogue: exchange via smem, then pointwise ----------------
    cp_wait<0>();
    __syncthreads();
    float* eps = reinterpret_cast<float*>(smem);

    // store accumulators: eps[row][gate*64 + col]
#pragma unroll
    for (int i = 0; i < 4; i++) {
        const int r0 = wr * 64 + i * 16 + (lid >> 2);
        const int r1 = r0 + 8;
#pragma unroll
        for (int n8 = 0; n8 < 8; n8++) {
            const int coloff = wc * 64 + n8 * 8 + (lid & 3) * 2;
            eps[r0 * EPS_STRIDE + coloff]     = acc[i][n8][0];
            eps[r0 * EPS_STRIDE + coloff + 1] = acc[i][n8][1];
            eps[r1 * EPS_STRIDE + coloff]     = acc[i][n8][2];
            eps[r1 * EPS_STRIDE + coloff + 1] = acc[i][n8][3];
        }
    }
    // bias sums: 4 gates x 64 cols
    {
        const int g = tid >> 6, cc = tid & 63;
        eps[BIAS_OFF + tid] = b_ih[g * HID_ + n0 + cc] + b_hh[g * HID_ + n0 + cc];
    }
    __syncthreads();

    // 8 passes: 16 rows x (16 lanes * 4 cols = 64 cols); coalesced 256B global writes
#pragma unroll 1
    for (int p = 0; p < 8; p++) {
        const int row = (tid >> 4) + p * 16;
        const int ct  = (tid & 15) * 4;
        const float* er = eps + row * EPS_STRIDE;
        const size_t gbase = (size_t)(m0 + row) * HID_ + n0 + ct;
        const float4 cv = *reinterpret_cast<const float4*>(cprev + gbase);
        float4 hn, cn;
#pragma unroll
        for (int j = 0; j < 4; j++) {
            const int cc = ct + j;
            const float gi = er[cc]        + eps[BIAS_OFF + cc];
            const float gf = er[64 + cc]   + eps[BIAS_OFF + 64 + cc];
            const float gc = er[128 + cc]  + eps[BIAS_OFF + 128 + cc];
            const float go = er[192 + cc]  + eps[BIAS_OFF + 192 + cc];
            const float ig = sigmoid_f(gi);
            const float fg = sigmoid_f(gf);
            const float cg = tanhf(gc);
            const float og = sigmoid_f(go);
            const float cpv = (j == 0) ? cv.x : (j == 1) ? cv.y : (j == 2) ? cv.z : cv.w;
            const float cnv = fg * cpv + ig * cg;
            const float hnv = og * tanhf(cnv);
            if (j == 0) { hn.x = hnv; cn.x = cnv; }
            else if (j == 1) { hn.y = hnv; cn.y = cnv; }
            else if (j == 2) { hn.z = hnv; cn.z = cnv; }
            else { hn.w = hnv; cn.w = cnv; }
        }
        *reinterpret_cast<float4*>(out + gbase)      = hn;
        *reinterpret_cast<float4*>(out + BH + gbase) = cn;
    }
}

// ---------------- launch ----------------
extern "C" void kernel_launch(void* const* d_in, const int* in_sizes, int n_in,
                              void* d_out, int out_size)
{
    (void)in_sizes; (void)n_in; (void)out_size;
    const float* x    = (const float*)d_in[0];
    const float* h    = (const float*)d_in[1];
    const float* c    = (const float*)d_in[2];
    const float* w_ih = (const float*)d_in[3];
    const float* w_hh = (const float*)d_in[4];
    const float* b_ih = (const float*)d_in[5];
    const float* b_hh = (const float*)d_in[6];
    float* out = (float*)d_out;

    // 1) merged conversion: z=0 -> A f16, z=1..4 -> weight transpose + f16 hi/lo split
    conv_kernel<<<dim3(64, 128, 5), 256>>>(x, h, w_ih, w_hh);

    // 2) fused tensor-core GEMM + LSTM epilogue (m-fastest grid for B-panel L2 reuse)
    cudaFuncSetAttribute(lstm_fused_kernel,
                         cudaFuncAttributeMaxDynamicSharedMemorySize, SMEM_TOTAL);
    dim3 gg(BATCH_ / BM, HID_ / BN);   // (32, 32)
    lstm_fused_kernel<<<gg, 256, SMEM_TOTAL>>>(c, b_ih, b_hh, out);
}

// round 13
// speedup vs baseline: 1.6894x; 1.6894x over previous
#include <cuda_runtime.h>
#include <cuda_fp16.h>
#include <cstdint>
#include <math.h>

#define BATCH_ 4096
#define HID_   2048
#define KTOT   4096            // K = INPUT(2048 from x) ++ HIDDEN(2048 from h)
#define NFLAT  8192            // 4 gates * 2048 flattened N
#define BH     ((size_t)BATCH_ * HID_)

// GEMM tiling: CTA = 128(m) x 128(nf); 8 warps in 2x4; warp tile 64x32
#define BM 128
#define BN 128
#define BK 32
#define STAGES 4
#define NKC (KTOT / BK)        // 128 k-iterations

// SMEM stage layout (24KB per stage, 4 stages = 96KB -> 2 CTAs/SM)
#define OFF_A   0
#define OFF_BHI 8192
#define OFF_BLO 16384
#define ST_BYTES 24576
#define SMEM_TOTAL (STAGES * ST_BYTES)

// ---------------- scratch (device globals; allocation-free) ----------------
__device__ __half g_A[(size_t)BATCH_ * KTOT];          // [b][k] f16       32MB
__device__ __half g_B_hi[(size_t)NFLAT * KTOT];        // [g*2048+n][k]    64MB
__device__ __half g_B_lo[(size_t)NFLAT * KTOT];        // f16 residual     64MB
__device__ float  g_gates[(size_t)4 * BATCH_ * HID_];  // [g][b][n]       134MB

// ---------------- PTX helpers (base ISA only) ----------------
__device__ __forceinline__ uint32_t smem_u32(const void* p) {
    uint32_t a;
    asm("{ .reg .u64 t; cvta.to.shared.u64 t, %1; cvt.u32.u64 %0, t; }" : "=r"(a) : "l"(p));
    return a;
}
__device__ __forceinline__ void cp16(uint32_t dst, const void* src) {
    asm volatile("cp.async.cg.shared.global [%0], [%1], 16;" :: "r"(dst), "l"(src));
}
__device__ __forceinline__ void cp_commit() { asm volatile("cp.async.commit_group;" ::: "memory"); }
template <int N>
__device__ __forceinline__ void cp_wait() { asm volatile("cp.async.wait_group %0;" :: "n"(N) : "memory"); }

__device__ __forceinline__ void ldsm4(uint32_t* r, uint32_t addr) {
    asm volatile("ldmatrix.sync.aligned.m8n8.x4.shared.b16 {%0,%1,%2,%3}, [%4];"
                 : "=r"(r[0]), "=r"(r[1]), "=r"(r[2]), "=r"(r[3]) : "r"(addr));
}
__device__ __forceinline__ void mma16816(float* d, const uint32_t* a, uint32_t b0, uint32_t b1) {
    asm volatile(
        "mma.sync.aligned.m16n8k16.row.col.f32.f16.f16.f32 "
        "{%0,%1,%2,%3}, {%4,%5,%6,%7}, {%8,%9}, {%0,%1,%2,%3};"
        : "+f"(d[0]), "+f"(d[1]), "+f"(d[2]), "+f"(d[3])
        : "r"(a[0]), "r"(a[1]), "r"(a[2]), "r"(a[3]), "r"(b0), "r"(b1));
}

// 64B-row swizzle: conflict-free for cp.async 16B stores + ldmatrix (proven R10-R12)
__device__ __forceinline__ uint32_t sw64(int row, int k2) {
    return (uint32_t)(row * 64 + ((k2 ^ ((row >> 1) & 3)) << 4));
}

// ---------------- merged conversion kernel (proven R12) ----------------
// z==0      : A = f16(x | h)
// z in 1..4 : gate g=z-1, transpose+split weights -> Bt[g*2048+n][k] f16 hi/lo
__global__ __launch_bounds__(256) void conv_kernel(
    const float* __restrict__ x, const float* __restrict__ h,
    const float* __restrict__ w_ih, const float* __restrict__ w_hh)
{
    if (blockIdx.z == 0) {
        const int bid = blockIdx.y * 64 + blockIdx.x;            // 0..8191
        const size_t e = ((size_t)bid * 256 + threadIdx.x) * 4;  // < 4096*2048
        const int row = (int)(e >> 11);
        const int col = (int)(e & 2047);
        const float4 xv = *reinterpret_cast<const float4*>(x + e);
        const float4 hv = *reinterpret_cast<const float4*>(h + e);
        const size_t base = (size_t)row * KTOT + col;
        __half2* a0 = reinterpret_cast<__half2*>(g_A + base);
        __half2* a1 = reinterpret_cast<__half2*>(g_A + base + 2048);
        a0[0] = __floats2half2_rn(xv.x, xv.y);
        a0[1] = __floats2half2_rn(xv.z, xv.w);
        a1[0] = __floats2half2_rn(hv.x, hv.y);
        a1[1] = __floats2half2_rn(hv.z, hv.w);
    } else {
        __shared__ float t[32][33];
        const int g = blockIdx.z - 1;
        const int nt = blockIdx.x * 32;      // 64 blocks * 32 = 2048
        const int kt = blockIdx.y * 32;      // 128 blocks * 32 = 4096
        const int tx = threadIdx.x & 31;
        const int ty = threadIdx.x >> 5;     // 0..7
#pragma unroll
        for (int r = 0; r < 4; r++) {
            const int kk = kt + ty + r * 8;
            const float* src = (kk < 2048)
                ? (w_ih + ((size_t)g * 2048 + kk) * HID_)
                : (w_hh + ((size_t)g * 2048 + (kk - 2048)) * HID_);
            t[ty + r * 8][tx] = src[nt + tx];
        }
        __syncthreads();
#pragma unroll
        for (int r = 0; r < 4; r++) {
            const int nn = nt + ty + r * 8;
            const float v = t[tx][ty + r * 8];
            const __half hi = __float2half_rn(v);
            const __half lo = __float2half_rn(v - __half2float(hi));
            const size_t off = ((size_t)g * HID_ + nn) * KTOT + kt + tx;
            g_B_hi[off] = hi;
            g_B_lo[off] = lo;
        }
    }
}

// ---------------- f16 2-split tensor-core GEMM (occupancy 2) ----------------
__global__ __launch_bounds__(256, 2) void gates_mma_kernel() {
    extern __shared__ char smem[];
    const uint32_t sb = smem_u32(smem);
    const int tid = threadIdx.x;
    const int wid = tid >> 5;
    const int lid = tid & 31;
    const int wr = wid >> 2;       // 0..1  (64-row m band)
    const int wc = wid & 3;        // 0..3  (32-col n band)
    const int m0 = blockIdx.x * BM;
    const int n0f = blockIdx.y * BN;

    // ---- producer per-thread constants ----
    // A: 128 rows x 4 k2 = 512 x 16B; 2 chunks/thread. B rows 0..127 likewise.
    size_t gA[2], gB[2]; uint32_t oAB[2];
#pragma unroll
    for (int j = 0; j < 2; j++) {
        const int idx = tid + j * 256;
        const int r = idx >> 2, k2 = idx & 3;
        oAB[j] = sw64(r, k2);
        gA[j] = (size_t)(m0 + r) * KTOT + k2 * 8;
        gB[j] = (size_t)(n0f + r) * KTOT + k2 * 8;
    }

    // ---- consumer ldmatrix offsets (ko=0; ko=1 == ^32) ----
    const int lrow = lid & 15;
    const int lk2  = lid >> 4;
    uint32_t aOff[4], bOff[2];
#pragma unroll
    for (int i = 0; i < 4; i++)    aOff[i]  = sw64(wr * 64 + i * 16 + lrow, lk2);
#pragma unroll
    for (int nt = 0; nt < 2; nt++) bOff[nt] = sw64(wc * 32 + nt * 16 + lrow, lk2);

    float acc[4][4][4];
#pragma unroll
    for (int i = 0; i < 4; i++)
#pragma unroll
        for (int j = 0; j < 4; j++)
#pragma unroll
            for (int p = 0; p < 4; p++) acc[i][j][p] = 0.0f;

    auto load_stage = [&](int kt) {
        const uint32_t base = sb + (uint32_t)(kt & (STAGES - 1)) * ST_BYTES;
        const int k0 = kt * BK;
#pragma unroll
        for (int j = 0; j < 2; j++) {
            cp16(base + OFF_A   + oAB[j], g_A    + gA[j] + k0);
            cp16(base + OFF_BHI + oAB[j], g_B_hi + gB[j] + k0);
            cp16(base + OFF_BLO + oAB[j], g_B_lo + gB[j] + k0);
        }
    };

#pragma unroll
    for (int kt = 0; kt < STAGES - 1; kt++) { load_stage(kt); cp_commit(); }

    for (int kt = 0; kt < NKC; kt++) {
        cp_wait<STAGES - 2>();
        __syncthreads();           // stage kt ready; WAR-guards refill of stage (kt+3)&3

        // issue next stage's loads first so DMA overlaps the whole MMA burst
        const int np = kt + STAGES - 1;
        if (np < NKC) load_stage(np);
        cp_commit();

        const uint32_t base = sb + (uint32_t)(kt & (STAGES - 1)) * ST_BYTES;

#pragma unroll
        for (int ko = 0; ko < 2; ko++) {           // two k16 steps per k32 stage
            const uint32_t x32 = ko ? 32u : 0u;
            uint32_t a[4][4], bh[2][4], bl[2][4];
#pragma unroll
            for (int i = 0; i < 4; i++)
                ldsm4(a[i], base + OFF_A + (aOff[i] ^ x32));
#pragma unroll
            for (int nt = 0; nt < 2; nt++) {
                ldsm4(bh[nt], base + OFF_BHI + (bOff[nt] ^ x32));
                ldsm4(bl[nt], base + OFF_BLO + (bOff[nt] ^ x32));
            }
            // pass 1: a * b_hi  (16 independent MMAs)
#pragma unroll
            for (int nt = 0; nt < 2; nt++)
#pragma unroll
                for (int i = 0; i < 4; i++) {
                    mma16816(acc[i][2 * nt],     a[i], bh[nt][0], bh[nt][2]);
                    mma16816(acc[i][2 * nt + 1], a[i], bh[nt][1], bh[nt][3]);
                }
            // pass 2: a * b_lo
#pragma unroll
            for (int nt = 0; nt < 2; nt++)
#pragma unroll
                for (int i = 0; i < 4; i++) {
                    mma16816(acc[i][2 * nt],     a[i], bl[nt][0], bl[nt][2]);
                    mma16816(acc[i][2 * nt + 1], a[i], bl[nt][1], bl[nt][3]);
                }
        }
    }

    // Store to g_gates[g][b][n]; CTA's 128 n-cols sit inside one gate (2048 % 128 == 0)
    const int g = n0f >> 11;
    const int nb = (n0f & 2047) + wc * 32 + (lid & 3) * 2;
    float* __restrict__ gp = g_gates + (size_t)g * BH;
#pragma unroll
    for (int i = 0; i < 4; i++) {
        const int r0 = m0 + wr * 64 + i * 16 + (lid >> 2);
#pragma unroll
        for (int n8 = 0; n8 < 4; n8++) {
            const int col = nb + n8 * 8;
            float2 v0; v0.x = acc[i][n8][0]; v0.y = acc[i][n8][1];
            float2 v1; v1.x = acc[i][n8][2]; v1.y = acc[i][n8][3];
            *reinterpret_cast<float2*>(gp + (size_t)r0 * HID_ + col)       = v0;
            *reinterpret_cast<float2*>(gp + (size_t)(r0 + 8) * HID_ + col) = v1;
        }
    }
}

// ---------------- epilogue (proven R8/R10: ~44us) ----------------
__device__ __forceinline__ float sigmoid_f(float v) { return 1.0f / (1.0f + expf(-v)); }

__device__ __forceinline__ void lstm_one(float gi, float gf, float gc, float go,
                                         float cprev, float& hn, float& cn) {
    const float ig = sigmoid_f(gi);
    const float fg = sigmoid_f(gf);
    const float cg = tanhf(gc);
    const float og = sigmoid_f(go);
    cn = fg * cprev + ig * cg;
    hn = og * tanhf(cn);
}

__global__ __launch_bounds__(256) void lstm_epilogue_kernel(
    const float* __restrict__ c,
    const float* __restrict__ b_ih, const float* __restrict__ b_hh,
    float* __restrict__ out)
{
    const size_t idx = ((size_t)blockIdx.x * blockDim.x + threadIdx.x) * 4;
    if (idx >= BH) return;
    const int n = (int)(idx & (HID_ - 1));

    const float4 g0 = *reinterpret_cast<const float4*>(&g_gates[idx]);
    const float4 g1 = *reinterpret_cast<const float4*>(&g_gates[BH + idx]);
    const float4 g2 = *reinterpret_cast<const float4*>(&g_gates[2 * BH + idx]);
    const float4 g3 = *reinterpret_cast<const float4*>(&g_gates[3 * BH + idx]);

    const float4 bi0 = *reinterpret_cast<const float4*>(&b_ih[0 * HID_ + n]);
    const float4 bi1 = *reinterpret_cast<const float4*>(&b_ih[1 * HID_ + n]);
    const float4 bi2 = *reinterpret_cast<const float4*>(&b_ih[2 * HID_ + n]);
    const float4 bi3 = *reinterpret_cast<const float4*>(&b_ih[3 * HID_ + n]);
    const float4 bh0 = *reinterpret_cast<const float4*>(&b_hh[0 * HID_ + n]);
    const float4 bh1 = *reinterpret_cast<const float4*>(&b_hh[1 * HID_ + n]);
    const float4 bh2 = *reinterpret_cast<const float4*>(&b_hh[2 * HID_ + n]);
    const float4 bh3 = *reinterpret_cast<const float4*>(&b_hh[3 * HID_ + n]);

    const float4 cv = *reinterpret_cast<const float4*>(&c[idx]);

    float4 hn, cn;
    lstm_one(g0.x + bi0.x + bh0.x, g1.x + bi1.x + bh1.x,
             g2.x + bi2.x + bh2.x, g3.x + bi3.x + bh3.x, cv.x, hn.x, cn.x);
    lstm_one(g0.y + bi0.y + bh0.y, g1.y + bi1.y + bh1.y,
             g2.y + bi2.y + bh2.y, g3.y + bi3.y + bh3.y, cv.y, hn.y, cn.y);
    lstm_one(g0.z + bi0.z + bh0.z, g1.z + bi1.z + bh1.z,
             g2.z + bi2.z + bh2.z, g3.z + bi3.z + bh3.z, cv.z, hn.z, cn.z);
    lstm_one(g0.w + bi0.w + bh0.w, g1.w + bi1.w + bh1.w,
             g2.w + bi2.w + bh2.w, g3.w + bi3.w + bh3.w, cv.w, hn.w, cn.w);

    *reinterpret_cast<float4*>(&out[idx])      = hn;
    *reinterpret_cast<float4*>(&out[BH + idx]) = cn;
}

// ---------------- launch ----------------
extern "C" void kernel_launch(void* const* d_in, const int* in_sizes, int n_in,
                              void* d_out, int out_size)
{
    (void)in_sizes; (void)n_in; (void)out_size;
    const float* x    = (const float*)d_in[0];
    const float* h    = (const float*)d_in[1];
    const float* c    = (const float*)d_in[2];
    const float* w_ih = (const float*)d_in[3];
    const float* w_hh = (const float*)d_in[4];
    const float* b_ih = (const float*)d_in[5];
    const float* b_hh = (const float*)d_in[6];
    float* out = (float*)d_out;

    // 1) merged conversion: z=0 -> A f16, z=1..4 -> weight transpose + f16 hi/lo split
    conv_kernel<<<dim3(64, 128, 5), 256>>>(x, h, w_ih, w_hh);

    // 2) tensor-core GEMM, 2 CTAs/SM (m-fastest grid for B-panel L2 reuse)
    cudaFuncSetAttribute(gates_mma_kernel,
                         cudaFuncAttributeMaxDynamicSharedMemorySize, SMEM_TOTAL);
    dim3 gg(BATCH_ / BM, NFLAT / BN);   // (32, 64)
    gates_mma_kernel<<<gg, 256, SMEM_TOTAL>>>();

    // 3) fused LSTM pointwise epilogue
    lstm_epilogue_kernel<<<(int)(BH / 4 / 256), 256>>>(c, b_ih, b_hh, out);
}

// round 14
// speedup vs baseline: 3.2233x; 1.9079x over previous
#include <cuda_runtime.h>
#include <cuda_fp16.h>
#include <cstdint>
#include <math.h>

#define BATCH_ 4096
#define HID_   2048
#define KTOT   4096            // K = INPUT(2048 from x) ++ HIDDEN(2048 from h)
#define NFLAT  8192            // 4 gates * 2048 flattened N
#define BH     ((size_t)BATCH_ * HID_)

// GEMM tiling: CTA = 128(m) x 128(nf) x 64(k); 8 warps in 2x4; warp tile 64x32
#define BM 128
#define BN 128
#define BK 64
#define STAGES 3
#define NKC (KTOT / BK)        // 64 k-iterations

// SMEM stage layout (32KB per stage, 3 stages = 96KB -> 2 CTAs/SM)
#define OFF_A  0
#define OFF_B  16384
#define ST_BYTES 32768
#define SMEM_TOTAL (STAGES * ST_BYTES)

// ---------------- scratch (device globals; allocation-free) ----------------
__device__ __half g_A[(size_t)BATCH_ * KTOT];          // [b][k] f16       32MB
__device__ __half g_B[(size_t)NFLAT * KTOT];           // [g*2048+n][k]    64MB
__device__ float  g_gates[(size_t)4 * BATCH_ * HID_];  // [g][b][n]       134MB

// ---------------- PTX helpers (base ISA only) ----------------
__device__ __forceinline__ uint32_t smem_u32(const void* p) {
    uint32_t a;
    asm("{ .reg .u64 t; cvta.to.shared.u64 t, %1; cvt.u32.u64 %0, t; }" : "=r"(a) : "l"(p));
    return a;
}
__device__ __forceinline__ void cp16(uint32_t dst, const void* src) {
    asm volatile("cp.async.cg.shared.global [%0], [%1], 16;" :: "r"(dst), "l"(src));
}
__device__ __forceinline__ void cp_commit() { asm volatile("cp.async.commit_group;" ::: "memory"); }
template <int N>
__device__ __forceinline__ void cp_wait() { asm volatile("cp.async.wait_group %0;" :: "n"(N) : "memory"); }

__device__ __forceinline__ void ldsm4(uint32_t* r, uint32_t addr) {
    asm volatile("ldmatrix.sync.aligned.m8n8.x4.shared.b16 {%0,%1,%2,%3}, [%4];"
                 : "=r"(r[0]), "=r"(r[1]), "=r"(r[2]), "=r"(r[3]) : "r"(addr));
}
__device__ __forceinline__ void mma16816(float* d, const uint32_t* a, uint32_t b0, uint32_t b1) {
    asm volatile(
        "mma.sync.aligned.m16n8k16.row.col.f32.f16.f16.f32 "
        "{%0,%1,%2,%3}, {%4,%5,%6,%7}, {%8,%9}, {%0,%1,%2,%3};"
        : "+f"(d[0]), "+f"(d[1]), "+f"(d[2]), "+f"(d[3])
        : "r"(a[0]), "r"(a[1]), "r"(a[2]), "r"(a[3]), "r"(b0), "r"(b1));
}

// 128B-row swizzle: k2 (16B column, 0..7) XOR row&7 -> conflict-free for
// cp.async 16B stores and ldmatrix 8-row phases. ko-step == addr ^ (ko<<5).
__device__ __forceinline__ uint32_t sw128(int row, int k2) {
    return (uint32_t)(row * 128 + ((k2 ^ (row & 7)) << 4));
}

// ---------------- merged conversion kernel ----------------
// z==0      : A = f16(x | h)
// z in 1..4 : gate g=z-1, transpose weights -> Bt[g*2048+n][k] f16
__global__ __launch_bounds__(256) void conv_kernel(
    const float* __restrict__ x, const float* __restrict__ h,
    const float* __restrict__ w_ih, const float* __restrict__ w_hh)
{
    if (blockIdx.z == 0) {
        const int bid = blockIdx.y * 64 + blockIdx.x;            // 0..8191
        const size_t e = ((size_t)bid * 256 + threadIdx.x) * 4;  // < 4096*2048
        const int row = (int)(e >> 11);
        const int col = (int)(e & 2047);
        const float4 xv = *reinterpret_cast<const float4*>(x + e);
        const float4 hv = *reinterpret_cast<const float4*>(h + e);
        const size_t base = (size_t)row * KTOT + col;
        __half2* a0 = reinterpret_cast<__half2*>(g_A + base);
        __half2* a1 = reinterpret_cast<__half2*>(g_A + base + 2048);
        a0[0] = __floats2half2_rn(xv.x, xv.y);
        a0[1] = __floats2half2_rn(xv.z, xv.w);
        a1[0] = __floats2half2_rn(hv.x, hv.y);
        a1[1] = __floats2half2_rn(hv.z, hv.w);
    } else {
        __shared__ float t[32][33];
        const int g = blockIdx.z - 1;
        const int nt = blockIdx.x * 32;      // 64 blocks * 32 = 2048
        const int kt = blockIdx.y * 32;      // 128 blocks * 32 = 4096
        const int tx = threadIdx.x & 31;
        const int ty = threadIdx.x >> 5;     // 0..7
#pragma unroll
        for (int r = 0; r < 4; r++) {
            const int kk = kt + ty + r * 8;
            const float* src = (kk < 2048)
                ? (w_ih + ((size_t)g * 2048 + kk) * HID_)
                : (w_hh + ((size_t)g * 2048 + (kk - 2048)) * HID_);
            t[ty + r * 8][tx] = src[nt + tx];
        }
        __syncthreads();
#pragma unroll
        for (int r = 0; r < 4; r++) {
            const int nn = nt + ty + r * 8;
            g_B[((size_t)g * HID_ + nn) * KTOT + kt + tx] =
                __float2half_rn(t[tx][ty + r * 8]);
        }
    }
}

// ---------------- single-pass f16 tensor-core GEMM (occupancy 2) ----------------
__global__ __launch_bounds__(256, 2) void gates_mma_kernel() {
    extern __shared__ char smem[];
    const uint32_t sb = smem_u32(smem);
    const int tid = threadIdx.x;
    const int wid = tid >> 5;
    const int lid = tid & 31;
    const int wr = wid >> 2;       // 0..1  (64-row m band)
    const int wc = wid & 3;        // 0..3  (32-col n band)
    const int m0 = blockIdx.x * BM;
    const int n0f = blockIdx.y * BN;

    // ---- producer per-thread constants ----
    // per stage: A 128 rows x 8 chunks = 1024 x 16B, B likewise; 4 chunks each/thread
    size_t gA[4], gB[4]; uint32_t oAB[4];
#pragma unroll
    for (int j = 0; j < 4; j++) {
        const int idx = tid + j * 256;
        const int r = idx >> 3, k2 = idx & 7;
        oAB[j] = sw128(r, k2);
        gA[j] = (size_t)(m0 + r) * KTOT + k2 * 8;
        gB[j] = (size_t)(n0f + r) * KTOT + k2 * 8;
    }

    // ---- consumer ldmatrix offsets (ko=0; step ko == ^ (ko<<5)) ----
    const int lrow = lid & 15;
    const int lk2  = lid >> 4;
    uint32_t aOff[4], bOff[2];
#pragma unroll
    for (int i = 0; i < 4; i++)    aOff[i]  = sw128(wr * 64 + i * 16 + lrow, lk2);
#pragma unroll
    for (int nt = 0; nt < 2; nt++) bOff[nt] = sw128(wc * 32 + nt * 16 + lrow, lk2);

    float acc[4][4][4];
#pragma unroll
    for (int i = 0; i < 4; i++)
#pragma unroll
        for (int j = 0; j < 4; j++)
#pragma unroll
            for (int p = 0; p < 4; p++) acc[i][j][p] = 0.0f;

    auto load_stage = [&](int kt, int st) {
        const uint32_t base = sb + (uint32_t)st * ST_BYTES;
        const int k0 = kt * BK;
#pragma unroll
        for (int j = 0; j < 4; j++) {
            cp16(base + OFF_A + oAB[j], g_A + gA[j] + k0);
            cp16(base + OFF_B + oAB[j], g_B + gB[j] + k0);
        }
    };

    load_stage(0, 0); cp_commit();
    load_stage(1, 1); cp_commit();

    int st = 0;                         // stage of current kt
    for (int kt = 0; kt < NKC; kt++) {
        cp_wait<STAGES - 2>();          // current stage's group retired
        __syncthreads();                // all warps done with the stage being refilled

        const int np = kt + STAGES - 1; // prefetch 2 ahead
        const int pst = (st == 0) ? 2 : st - 1;   // (st + 2) % 3
        if (np < NKC) load_stage(np, pst);
        cp_commit();

        const uint32_t base = sb + (uint32_t)st * ST_BYTES;

#pragma unroll
        for (int ko = 0; ko < 4; ko++) {           // four k16 steps per k64 stage
            const uint32_t kx = (uint32_t)ko << 5;
            uint32_t a[4][4], b[2][4];
#pragma unroll
            for (int i = 0; i < 4; i++)
                ldsm4(a[i], base + OFF_A + (aOff[i] ^ kx));
#pragma unroll
            for (int nt = 0; nt < 2; nt++)
                ldsm4(b[nt], base + OFF_B + (bOff[nt] ^ kx));
#pragma unroll
            for (int nt = 0; nt < 2; nt++)
#pragma unroll
                for (int i = 0; i < 4; i++) {
                    mma16816(acc[i][2 * nt],     a[i], b[nt][0], b[nt][2]);
                    mma16816(acc[i][2 * nt + 1], a[i], b[nt][1], b[nt][3]);
                }
        }
        st = (st == 2) ? 0 : st + 1;
    }

    // Store to g_gates[g][b][n]; CTA's 128 n-cols sit inside one gate
    const int g = n0f >> 11;
    const int nb = (n0f & 2047) + wc * 32 + (lid & 3) * 2;
    float* __restrict__ gp = g_gates + (size_t)g * BH;
#pragma unroll
    for (int i = 0; i < 4; i++) {
        const int r0 = m0 + wr * 64 + i * 16 + (lid >> 2);
#pragma unroll
        for (int n8 = 0; n8 < 4; n8++) {
            const int col = nb + n8 * 8;
            float2 v0; v0.x = acc[i][n8][0]; v0.y = acc[i][n8][1];
            float2 v1; v1.x = acc[i][n8][2]; v1.y = acc[i][n8][3];
            *reinterpret_cast<float2*>(gp + (size_t)r0 * HID_ + col)       = v0;
            *reinterpret_cast<float2*>(gp + (size_t)(r0 + 8) * HID_ + col) = v1;
        }
    }
}

// ---------------- epilogue (proven R8/R10/R13: ~44us) ----------------
__device__ __forceinline__ float sigmoid_f(float v) { return 1.0f / (1.0f + expf(-v)); }

__device__ __forceinline__ void lstm_one(float gi, float gf, float gc, float go,
                                         float cprev, float& hn, float& cn) {
    const float ig = sigmoid_f(gi);
    const float fg = sigmoid_f(gf);
    const float cg = tanhf(gc);
    const float og = sigmoid_f(go);
    cn = fg * cprev + ig * cg;
    hn = og * tanhf(cn);
}

__global__ __launch_bounds__(256) void lstm_epilogue_kernel(
    const float* __restrict__ c,
    const float* __restrict__ b_ih, const float* __restrict__ b_hh,
    float* __restrict__ out)
{
    const size_t idx = ((size_t)blockIdx.x * blockDim.x + threadIdx.x) * 4;
    if (idx >= BH) return;
    const int n = (int)(idx & (HID_ - 1));

    const float4 g0 = *reinterpret_cast<const float4*>(&g_gates[idx]);
    const float4 g1 = *reinterpret_cast<const float4*>(&g_gates[BH + idx]);
    const float4 g2 = *reinterpret_cast<const float4*>(&g_gates[2 * BH + idx]);
    const float4 g3 = *reinterpret_cast<const float4*>(&g_gates[3 * BH + idx]);

    const float4 bi0 = *reinterpret_cast<const float4*>(&b_ih[0 * HID_ + n]);
    const float4 bi1 = *reinterpret_cast<const float4*>(&b_ih[1 * HID_ + n]);
    const float4 bi2 = *reinterpret_cast<const float4*>(&b_ih[2 * HID_ + n]);
    const float4 bi3 = *reinterpret_cast<const float4*>(&b_ih[3 * HID_ + n]);
    const float4 bh0 = *reinterpret_cast<const float4*>(&b_hh[0 * HID_ + n]);
    const float4 bh1 = *reinterpret_cast<const float4*>(&b_hh[1 * HID_ + n]);
    const float4 bh2 = *reinterpret_cast<const float4*>(&b_hh[2 * HID_ + n]);
    const float4 bh3 = *reinterpret_cast<const float4*>(&b_hh[3 * HID_ + n]);

    const float4 cv = *reinterpret_cast<const float4*>(&c[idx]);

    float4 hn, cn;
    lstm_one(g0.x + bi0.x + bh0.x, g1.x + bi1.x + bh1.x,
             g2.x + bi2.x + bh2.x, g3.x + bi3.x + bh3.x, cv.x, hn.x, cn.x);
    lstm_one(g0.y + bi0.y + bh0.y, g1.y + bi1.y + bh1.y,
             g2.y + bi2.y + bh2.y, g3.y + bi3.y + bh3.y, cv.y, hn.y, cn.y);
    lstm_one(g0.z + bi0.z + bh0.z, g1.z + bi1.z + bh1.z,
             g2.z + bi2.z + bh2.z, g3.z + bi3.z + bh3.z, cv.z, hn.z, cn.z);
    lstm_one(g0.w + bi0.w + bh0.w, g1.w + bi1.w + bh1.w,
             g2.w + bi2.w + bh2.w, g3.w + bi3.w + bh3.w, cv.w, hn.w, cn.w);

    *reinterpret_cast<float4*>(&out[idx])      = hn;
    *reinterpret_cast<float4*>(&out[BH + idx]) = cn;
}

// ---------------- launch ----------------
extern "C" void kernel_launch(void* const* d_in, const int* in_sizes, int n_in,
                              void* d_out, int out_size)
{
    (void)in_sizes; (void)n_in; (void)out_size;
    const float* x    = (const float*)d_in[0];
    const float* h    = (const float*)d_in[1];
    const float* c    = (const float*)d_in[2];
    const float* w_ih = (const float*)d_in[3];
    const float* w_hh = (const float*)d_in[4];
    const float* b_ih = (const float*)d_in[5];
    const float* b_hh = (const float*)d_in[6];
    float* out = (float*)d_out;

    // 1) merged conversion: z=0 -> A f16, z=1..4 -> weight transpose f16
    conv_kernel<<<dim3(64, 128, 5), 256>>>(x, h, w_ih, w_hh);

    // 2) single-pass f16 tensor-core GEMM, 2 CTAs/SM (m-fastest grid for L2 reuse)
    cudaFuncSetAttribute(gates_mma_kernel,
                         cudaFuncAttributeMaxDynamicSharedMemorySize, SMEM_TOTAL);
    dim3 gg(BATCH_ / BM, NFLAT / BN);   // (32, 64)
    gates_mma_kernel<<<gg, 256, SMEM_TOTAL>>>();

    // 3) fused LSTM pointwise epilogue
    lstm_epilogue_kernel<<<(int)(BH / 4 / 256), 256>>>(c, b_ih, b_hh, out);
}

// round 15
// speedup vs baseline: 3.2752x; 1.0161x over previous
#include <cuda_runtime.h>
#include <cuda_fp16.h>
#include <cstdint>
#include <math.h>

#define BATCH_ 4096
#define HID_   2048
#define KTOT   4096            // K = INPUT(2048 from x) ++ HIDDEN(2048 from h)
#define BH     ((size_t)BATCH_ * HID_)

// GEMM tiling: CTA = 128(m) x [32(n) x 4 gates](128 B-rows) x 64(k)
// 8 warps in 2x4; warp tile 64(m) x 32(n-within-gate); wc == gate index
#define BM 128
#define BK 64
#define STAGES 3
#define NKC (KTOT / BK)        // 64 k-iterations

// SMEM stage layout (32KB per stage, 3 stages = 96KB -> 2 CTAs/SM)
#define OFF_A  0
#define OFF_B  16384
#define ST_BYTES 32768
#define SMEM_TOTAL (STAGES * ST_BYTES)

// Epilogue exchange layout (reuses stage smem after the mainloop)
#define EPSS     132                    // floats per m-row (4 gates x 32 cols + pad)
#define BIAS_OFF (128 * EPSS)           // 128 bias floats after the tile

// ---------------- scratch (device globals; allocation-free) ----------------
__device__ __half g_A[(size_t)BATCH_ * KTOT];      // [b][k] f16          32MB
__device__ __half g_B[(size_t)4 * HID_ * KTOT];    // [g*2048+n][k] f16   64MB

// ---------------- PTX helpers (base ISA only) ----------------
__device__ __forceinline__ uint32_t smem_u32(const void* p) {
    uint32_t a;
    asm("{ .reg .u64 t; cvta.to.shared.u64 t, %1; cvt.u32.u64 %0, t; }" : "=r"(a) : "l"(p));
    return a;
}
__device__ __forceinline__ void cp16(uint32_t dst, const void* src) {
    asm volatile("cp.async.cg.shared.global [%0], [%1], 16;" :: "r"(dst), "l"(src));
}
__device__ __forceinline__ void cp_commit() { asm volatile("cp.async.commit_group;" ::: "memory"); }
template <int N>
__device__ __forceinline__ void cp_wait() { asm volatile("cp.async.wait_group %0;" :: "n"(N) : "memory"); }

__device__ __forceinline__ void ldsm4(uint32_t* r, uint32_t addr) {
    asm volatile("ldmatrix.sync.aligned.m8n8.x4.shared.b16 {%0,%1,%2,%3}, [%4];"
                 : "=r"(r[0]), "=r"(r[1]), "=r"(r[2]), "=r"(r[3]) : "r"(addr));
}
__device__ __forceinline__ void mma16816(float* d, const uint32_t* a, uint32_t b0, uint32_t b1) {
    asm volatile(
        "mma.sync.aligned.m16n8k16.row.col.f32.f16.f16.f32 "
        "{%0,%1,%2,%3}, {%4,%5,%6,%7}, {%8,%9}, {%0,%1,%2,%3};"
        : "+f"(d[0]), "+f"(d[1]), "+f"(d[2]), "+f"(d[3])
        : "r"(a[0]), "r"(a[1]), "r"(a[2]), "r"(a[3]), "r"(b0), "r"(b1));
}

// 128B-row swizzle: k2 (16B column, 0..7) XOR row&7 -> conflict-free for
// cp.async 16B stores and ldmatrix 8-row phases. ko-step == addr ^ (ko<<5).
__device__ __forceinline__ uint32_t sw128(int row, int k2) {
    return (uint32_t)(row * 128 + ((k2 ^ (row & 7)) << 4));
}

// ---------------- merged conversion kernel (proven R14) ----------------
// z==0      : A = f16(x | h)
// z in 1..4 : gate g=z-1, transpose weights -> Bt[g*2048+n][k] f16
__global__ __launch_bounds__(256) void conv_kernel(
    const float* __restrict__ x, const float* __restrict__ h,
    const float* __restrict__ w_ih, const float* __restrict__ w_hh)
{
    if (blockIdx.z == 0) {
        const int bid = blockIdx.y * 64 + blockIdx.x;            // 0..8191
        const size_t e = ((size_t)bid * 256 + threadIdx.x) * 4;  // < 4096*2048
        const int row = (int)(e >> 11);
        const int col = (int)(e & 2047);
        const float4 xv = *reinterpret_cast<const float4*>(x + e);
        const float4 hv = *reinterpret_cast<const float4*>(h + e);
        const size_t base = (size_t)row * KTOT + col;
        __half2* a0 = reinterpret_cast<__half2*>(g_A + base);
        __half2* a1 = reinterpret_cast<__half2*>(g_A + base + 2048);
        a0[0] = __floats2half2_rn(xv.x, xv.y);
        a0[1] = __floats2half2_rn(xv.z, xv.w);
        a1[0] = __floats2half2_rn(hv.x, hv.y);
        a1[1] = __floats2half2_rn(hv.z, hv.w);
    } else {
        __shared__ float t[32][33];
        const int g = blockIdx.z - 1;
        const int nt = blockIdx.x * 32;      // 64 blocks * 32 = 2048
        const int kt = blockIdx.y * 32;      // 128 blocks * 32 = 4096
        const int tx = threadIdx.x & 31;
        const int ty = threadIdx.x >> 5;     // 0..7
#pragma unroll
        for (int r = 0; r < 4; r++) {
            const int kk = kt + ty + r * 8;
            const float* src = (kk < 2048)
                ? (w_ih + ((size_t)g * 2048 + kk) * HID_)
                : (w_hh + ((size_t)g * 2048 + (kk - 2048)) * HID_);
            t[ty + r * 8][tx] = src[nt + tx];
        }
        __syncthreads();
#pragma unroll
        for (int r = 0; r < 4; r++) {
            const int nn = nt + ty + r * 8;
            g_B[((size_t)g * HID_ + nn) * KTOT + kt + tx] =
                __float2half_rn(t[tx][ty + r * 8]);
        }
    }
}

// ---------------- fused single-pass f16 GEMM + LSTM epilogue (occ 2) ----------------
__device__ __forceinline__ float sigmoid_f(float v) { return 1.0f / (1.0f + expf(-v)); }

__global__ __launch_bounds__(256, 2) void lstm_fused_kernel(
    const float* __restrict__ cprev, const float* __restrict__ b_ih,
    const float* __restrict__ b_hh, float* __restrict__ out)
{
    extern __shared__ char smem[];
    const uint32_t sb = smem_u32(smem);
    const int tid = threadIdx.x;
    const int wid = tid >> 5;
    const int lid = tid & 31;
    const int wr = wid >> 2;       // 0..1  (64-row m band)
    const int wc = wid & 3;        // 0..3  == GATE index (32-col n band of 128 B-rows)
    const int m0 = blockIdx.x * BM;
    const int n0 = blockIdx.y * 32;     // 32 hidden cols per CTA

    // ---- producer per-thread constants ----
    // per stage: A 128 rows x 8 chunks = 1024 x 16B, B likewise; 4 chunks each/thread
    // B row r (0..127): gate = r>>5, col = n0 + (r&31)
    size_t gA[4], gB[4]; uint32_t oAB[4];
#pragma unroll
    for (int j = 0; j < 4; j++) {
        const int idx = tid + j * 256;
        const int r = idx >> 3, k2 = idx & 7;
        oAB[j] = sw128(r, k2);
        gA[j] = (size_t)(m0 + r) * KTOT + k2 * 8;
        gB[j] = ((size_t)(r >> 5) * HID_ + n0 + (r & 31)) * KTOT + k2 * 8;
    }

    // ---- consumer ldmatrix offsets (ko=0; step ko == ^ (ko<<5)) ----
    const int lrow = lid & 15;
    const int lk2  = lid >> 4;
    uint32_t aOff[4], bOff[2];
#pragma unroll
    for (int i = 0; i < 4; i++)    aOff[i]  = sw128(wr * 64 + i * 16 + lrow, lk2);
#pragma unroll
    for (int nt = 0; nt < 2; nt++) bOff[nt] = sw128(wc * 32 + nt * 16 + lrow, lk2);

    float acc[4][4][4];
#pragma unroll
    for (int i = 0; i < 4; i++)
#pragma unroll
        for (int j = 0; j < 4; j++)
#pragma unroll
            for (int p = 0; p < 4; p++) acc[i][j][p] = 0.0f;

    auto load_stage = [&](int kt, int st) {
        const uint32_t base = sb + (uint32_t)st * ST_BYTES;
        const int k0 = kt * BK;
#pragma unroll
        for (int j = 0; j < 4; j++) {
            cp16(base + OFF_A + oAB[j], g_A + gA[j] + k0);
            cp16(base + OFF_B + oAB[j], g_B + gB[j] + k0);
        }
    };

    load_stage(0, 0); cp_commit();
    load_stage(1, 1); cp_commit();

    int st = 0;
    for (int kt = 0; kt < NKC; kt++) {
        cp_wait<STAGES - 2>();
        __syncthreads();                // stage kt ready; WAR-guards the refill below

        const int np = kt + STAGES - 1; // prefetch 2 ahead
        const int pst = (st == 0) ? 2 : st - 1;
        if (np < NKC) load_stage(np, pst);
        cp_commit();

        const uint32_t base = sb + (uint32_t)st * ST_BYTES;

#pragma unroll
        for (int ko = 0; ko < 4; ko++) {           // four k16 steps per k64 stage
            const uint32_t kx = (uint32_t)ko << 5;
            uint32_t a[4][4], b[2][4];
#pragma unroll
            for (int i = 0; i < 4; i++)
                ldsm4(a[i], base + OFF_A + (aOff[i] ^ kx));
#pragma unroll
            for (int nt = 0; nt < 2; nt++)
                ldsm4(b[nt], base + OFF_B + (bOff[nt] ^ kx));
#pragma unroll
            for (int nt = 0; nt < 2; nt++)
#pragma unroll
                for (int i = 0; i < 4; i++) {
                    mma16816(acc[i][2 * nt],     a[i], b[nt][0], b[nt][2]);
                    mma16816(acc[i][2 * nt + 1], a[i], b[nt][1], b[nt][3]);
                }
        }
        st = (st == 2) ? 0 : st + 1;
    }

    // ---------------- fused epilogue: exchange via smem, then pointwise ----------------
    cp_wait<0>();
    __syncthreads();
    float* eps = reinterpret_cast<float*>(smem);

    // store accumulators: eps[row][gate*32 + col]  (wc == gate)
#pragma unroll
    for (int i = 0; i < 4; i++) {
        const int r0 = wr * 64 + i * 16 + (lid >> 2);
        const int r1 = r0 + 8;
#pragma unroll
        for (int n8 = 0; n8 < 4; n8++) {
            const int coloff = wc * 32 + n8 * 8 + (lid & 3) * 2;
            eps[r0 * EPSS + coloff]     = acc[i][n8][0];
            eps[r0 * EPSS + coloff + 1] = acc[i][n8][1];
            eps[r1 * EPSS + coloff]     = acc[i][n8][2];
            eps[r1 * EPSS + coloff + 1] = acc[i][n8][3];
        }
    }
    // bias sums: 4 gates x 32 cols (threads 0..127)
    if (tid < 128) {
        const int g = tid >> 5, cc = tid & 31;
        eps[BIAS_OFF + tid] = b_ih[g * HID_ + n0 + cc] + b_hh[g * HID_ + n0 + cc];
    }
    __syncthreads();

    // 4 passes: 32 rows x (8 lanes * 4 cols = 32 cols); 128B-contiguous global writes
#pragma unroll 1
    for (int p = 0; p < 4; p++) {
        const int row = (tid >> 3) + p * 32;
        const int ct  = (tid & 7) * 4;
        const float* er = eps + row * EPSS;
        const size_t gbase = (size_t)(m0 + row) * HID_ + n0 + ct;
        const float4 cv = *reinterpret_cast<const float4*>(cprev + gbase);
        float4 hn, cn;
#pragma unroll
        for (int j = 0; j < 4; j++) {
            const int cc = ct + j;
            const float gi = er[cc]      + eps[BIAS_OFF + cc];
            const float gf = er[32 + cc] + eps[BIAS_OFF + 32 + cc];
            const float gc = er[64 + cc] + eps[BIAS_OFF + 64 + cc];
            const float go = er[96 + cc] + eps[BIAS_OFF + 96 + cc];
            const float ig = sigmoid_f(gi);
            const float fg = sigmoid_f(gf);
            const float cg = tanhf(gc);
            const float og = sigmoid_f(go);
            const float cpv = (j == 0) ? cv.x : (j == 1) ? cv.y : (j == 2) ? cv.z : cv.w;
            const float cnv = fg * cpv + ig * cg;
            const float hnv = og * tanhf(cnv);
            if (j == 0) { hn.x = hnv; cn.x = cnv; }
            else if (j == 1) { hn.y = hnv; cn.y = cnv; }
            else if (j == 2) { hn.z = hnv; cn.z = cnv; }
            else { hn.w = hnv; cn.w = cnv; }
        }
        *reinterpret_cast<float4*>(out + gbase)      = hn;
        *reinterpret_cast<float4*>(out + BH + gbase) = cn;
    }
}

// ---------------- launch ----------------
extern "C" void kernel_launch(void* const* d_in, const int* in_sizes, int n_in,
                              void* d_out, int out_size)
{
    (void)in_sizes; (void)n_in; (void)out_size;
    const float* x    = (const float*)d_in[0];
    const float* h    = (const float*)d_in[1];
    const float* c    = (const float*)d_in[2];
    const float* w_ih = (const float*)d_in[3];
    const float* w_hh = (const float*)d_in[4];
    const float* b_ih = (const float*)d_in[5];
    const float* b_hh = (const float*)d_in[6];
    float* out = (float*)d_out;

    // 1) merged conversion: z=0 -> A f16, z=1..4 -> weight transpose f16
    conv_kernel<<<dim3(64, 128, 5), 256>>>(x, h, w_ih, w_hh);

    // 2) fused single-pass f16 GEMM + LSTM epilogue, 2 CTAs/SM
    //    (m-fastest grid for B-panel L2 reuse)
    cudaFuncSetAttribute(lstm_fused_kernel,
                         cudaFuncAttributeMaxDynamicSharedMemorySize, SMEM_TOTAL);
    dim3 gg(BATCH_ / BM, HID_ / 32);   // (32, 64)
    lstm_fused_kernel<<<gg, 256, SMEM_TOTAL>>>(c, b_ih, b_hh, out);
}

// round 16
// speedup vs baseline: 3.4320x; 1.0479x over previous
#include <cuda_runtime.h>
#include <cuda_fp16.h>
#include <cstdint>
#include <math.h>

#define BATCH_ 4096
#define HID_   2048
#define KTOT   4096            // K = INPUT(2048 from x) ++ HIDDEN(2048 from h)
#define BH     ((size_t)BATCH_ * HID_)

// CTA = 64(m) x [32(n) x 4 gates](128 B-rows) x 64(k); 4 warps; warp = one gate,
// warp tile 64m x 32n. 2-stage ring, 4 CTAs/SM.
#define BM 64
#define BK 64
#define NKC (KTOT / BK)        // 64 k-iterations

// SMEM stage layout (24KB per stage, 2 stages = 48KB -> 4 CTAs/SM)
#define OFF_A  0
#define OFF_B  8192
#define ST_BYTES 24576
#define SMEM_TOTAL (2 * ST_BYTES)

// Epilogue exchange layout (reuses stage smem after the mainloop)
#define EPSS     133                    // floats per m-row (odd -> conflict-free)
#define BIAS_OFF (64 * EPSS)            // 128 bias floats after the 64-row tile

// ---------------- scratch (device globals; allocation-free) ----------------
__device__ __half g_A[(size_t)BATCH_ * KTOT];      // [b][k] f16          32MB
__device__ __half g_B[(size_t)4 * HID_ * KTOT];    // [g*2048+n][k] f16   64MB

// ---------------- PTX helpers (base ISA only) ----------------
__device__ __forceinline__ uint32_t smem_u32(const void* p) {
    uint32_t a;
    asm("{ .reg .u64 t; cvta.to.shared.u64 t, %1; cvt.u32.u64 %0, t; }" : "=r"(a) : "l"(p));
    return a;
}
__device__ __forceinline__ void cp16(uint32_t dst, const void* src) {
    asm volatile("cp.async.cg.shared.global [%0], [%1], 16;" :: "r"(dst), "l"(src));
}
__device__ __forceinline__ void cp_commit() { asm volatile("cp.async.commit_group;" ::: "memory"); }
template <int N>
__device__ __forceinline__ void cp_wait() { asm volatile("cp.async.wait_group %0;" :: "n"(N) : "memory"); }

__device__ __forceinline__ void ldsm4(uint32_t* r, uint32_t addr) {
    asm volatile("ldmatrix.sync.aligned.m8n8.x4.shared.b16 {%0,%1,%2,%3}, [%4];"
                 : "=r"(r[0]), "=r"(r[1]), "=r"(r[2]), "=r"(r[3]) : "r"(addr));
}
__device__ __forceinline__ void mma16816(float* d, const uint32_t* a, uint32_t b0, uint32_t b1) {
    asm volatile(
        "mma.sync.aligned.m16n8k16.row.col.f32.f16.f16.f32 "
        "{%0,%1,%2,%3}, {%4,%5,%6,%7}, {%8,%9}, {%0,%1,%2,%3};"
        : "+f"(d[0]), "+f"(d[1]), "+f"(d[2]), "+f"(d[3])
        : "r"(a[0]), "r"(a[1]), "r"(a[2]), "r"(a[3]), "r"(b0), "r"(b1));
}

// 128B-row swizzle: k2 (16B column, 0..7) XOR row&7 -> conflict-free for
// cp.async 16B stores and ldmatrix 8-row phases. ko-step == addr ^ (ko<<5).
__device__ __forceinline__ uint32_t sw128(int row, int k2) {
    return (uint32_t)(row * 128 + ((k2 ^ (row & 7)) << 4));
}

// ---------------- merged conversion kernel (proven R14/R15) ----------------
__global__ __launch_bounds__(256) void conv_kernel(
    const float* __restrict__ x, const float* __restrict__ h,
    const float* __restrict__ w_ih, const float* __restrict__ w_hh)
{
    if (blockIdx.z == 0) {
        const int bid = blockIdx.y * 64 + blockIdx.x;            // 0..8191
        const size_t e = ((size_t)bid * 256 + threadIdx.x) * 4;  // < 4096*2048
        const int row = (int)(e >> 11);
        const int col = (int)(e & 2047);
        const float4 xv = *reinterpret_cast<const float4*>(x + e);
        const float4 hv = *reinterpret_cast<const float4*>(h + e);
        const size_t base = (size_t)row * KTOT + col;
        __half2* a0 = reinterpret_cast<__half2*>(g_A + base);
        __half2* a1 = reinterpret_cast<__half2*>(g_A + base + 2048);
        a0[0] = __floats2half2_rn(xv.x, xv.y);
        a0[1] = __floats2half2_rn(xv.z, xv.w);
        a1[0] = __floats2half2_rn(hv.x, hv.y);
        a1[1] = __floats2half2_rn(hv.z, hv.w);
    } else {
        __shared__ float t[32][33];
        const int g = blockIdx.z - 1;
        const int nt = blockIdx.x * 32;      // 64 blocks * 32 = 2048
        const int kt = blockIdx.y * 32;      // 128 blocks * 32 = 4096
        const int tx = threadIdx.x & 31;
        const int ty = threadIdx.x >> 5;     // 0..7
#pragma unroll
        for (int r = 0; r < 4; r++) {
            const int kk = kt + ty + r * 8;
            const float* src = (kk < 2048)
                ? (w_ih + ((size_t)g * 2048 + kk) * HID_)
                : (w_hh + ((size_t)g * 2048 + (kk - 2048)) * HID_);
            t[ty + r * 8][tx] = src[nt + tx];
        }
        __syncthreads();
#pragma unroll
        for (int r = 0; r < 4; r++) {
            const int nn = nt + ty + r * 8;
            g_B[((size_t)g * HID_ + nn) * KTOT + kt + tx] =
                __float2half_rn(t[tx][ty + r * 8]);
        }
    }
}

// ---------------- fused f16 GEMM + LSTM epilogue (128 threads, 4 CTAs/SM) ----------------
__device__ __forceinline__ float sigmoid_f(float v) { return 1.0f / (1.0f + expf(-v)); }

__global__ __launch_bounds__(128, 4) void lstm_fused_kernel(
    const float* __restrict__ cprev, const float* __restrict__ b_ih,
    const float* __restrict__ b_hh, float* __restrict__ out)
{
    extern __shared__ char smem[];
    const uint32_t sb = smem_u32(smem);
    const int tid = threadIdx.x;
    const int wc = tid >> 5;       // warp == gate index, 0..3
    const int lid = tid & 31;
    const int m0 = blockIdx.x * BM;
    const int n0 = blockIdx.y * 32;     // 32 hidden cols per CTA

    // ---- producer constants (row-step j*16 preserves row&7 -> constant smem strides) ----
    // A: 64 rows x 8 k2-chunks = 512 x 16B; 4 chunks/thread (j=0..3, rows +16)
    // B: 128 rows x 8        = 1024 x 16B; 8 chunks/thread (j=0..7, gate j>>1, +16*(j&1))
    const int pr = tid >> 3;            // 0..15 (base row)
    const int pk = tid & 7;             // 16B column
    const uint32_t oA0 = sw128(pr, pk);               // + j*2048
    const uint32_t oB0 = (uint32_t)OFF_B + oA0;       // same row&7 pattern
    const size_t gA0 = (size_t)(m0 + pr) * KTOT + pk * 8;           // + j*16*KTOT
    const size_t gB0 = (size_t)(n0 + pr) * KTOT + pk * 8;  // + (j>>1)*HID*KTOT + (j&1)*16*KTOT

    // ---- consumer ldmatrix offsets (i/nt-step preserves row&7; ko-step == ^(ko<<5)) ----
    const uint32_t aOff0 = sw128(lid & 15, lid >> 4);                       // + i*2048
    const uint32_t bOff0 = (uint32_t)OFF_B + sw128(wc * 32 + (lid & 15), lid >> 4); // + nt*2048

    float acc[4][4][4];
#pragma unroll
    for (int i = 0; i < 4; i++)
#pragma unroll
        for (int j = 0; j < 4; j++)
#pragma unroll
            for (int p = 0; p < 4; p++) acc[i][j][p] = 0.0f;

    auto load_stage = [&](int kt, int st) {
        const uint32_t base = sb + (uint32_t)st * ST_BYTES;
        const int k0 = kt * BK;
#pragma unroll
        for (int j = 0; j < 4; j++)
            cp16(base + OFF_A + oA0 + j * 2048u,
                 g_A + gA0 + (size_t)j * 16 * KTOT + k0);
#pragma unroll
        for (int j = 0; j < 8; j++)
            cp16(base + oB0 + j * 2048u,
                 g_B + gB0 + (size_t)(j >> 1) * HID_ * KTOT + (size_t)(j & 1) * 16 * KTOT + k0);
    };

    load_stage(0, 0); cp_commit();
    load_stage(1, 1); cp_commit();
    cp_wait<1>();
    __syncthreads();        // stage 0 visible to all threads

    for (int kt = 0; kt < NKC; kt++) {
        const uint32_t base = sb + (uint32_t)(kt & 1) * ST_BYTES;

#pragma unroll
        for (int ko = 0; ko < 4; ko++) {           // four k16 steps per k64 stage
            const uint32_t kx = (uint32_t)ko << 5;
            uint32_t a[4][4], b[2][4];
#pragma unroll
            for (int i = 0; i < 4; i++)
                ldsm4(a[i], base + ((aOff0 + i * 2048u) ^ kx));
#pragma unroll
            for (int nt = 0; nt < 2; nt++)
                ldsm4(b[nt], base + ((bOff0 + nt * 2048u) ^ kx));
#pragma unroll
            for (int nt = 0; nt < 2; nt++)
#pragma unroll
                for (int i = 0; i < 4; i++) {
                    mma16816(acc[i][2 * nt],     a[i], b[nt][0], b[nt][2]);
                    mma16816(acc[i][2 * nt + 1], a[i], b[nt][1], b[nt][3]);
                }
        }

        __syncthreads();                 // all warps done reading stage kt&1
        if (kt + 2 < NKC) load_stage(kt + 2, kt & 1);
        cp_commit();                     // (possibly empty) keep group counts aligned
        cp_wait<1>();                    // stage kt+1's group retired
        __syncthreads();                 // ...and visible to all threads
    }

    // ---------------- fused epilogue: exchange via smem, then pointwise ----------------
    float* eps = reinterpret_cast<float*>(smem);

    // store accumulators: eps[row][gate*32 + col]  (wc == gate; rows 0..63)
#pragma unroll
    for (int i = 0; i < 4; i++) {
        const int r0 = i * 16 + (lid >> 2);
        const int r1 = r0 + 8;
#pragma unroll
        for (int n8 = 0; n8 < 4; n8++) {
            const int coloff = wc * 32 + n8 * 8 + (lid & 3) * 2;
            eps[r0 * EPSS + coloff]     = acc[i][n8][0];
            eps[r0 * EPSS + coloff + 1] = acc[i][n8][1];
            eps[r1 * EPSS + coloff]     = acc[i][n8][2];
            eps[r1 * EPSS + coloff + 1] = acc[i][n8][3];
        }
    }
    // bias sums: 4 gates x 32 cols (exactly 128 threads)
    {
        const int g = tid >> 5, cc = tid & 31;
        eps[BIAS_OFF + tid] = b_ih[g * HID_ + n0 + cc] + b_hh[g * HID_ + n0 + cc];
    }
    __syncthreads();

    // 4 passes: 16 rows x (8 lanes * 4 cols = 32 cols); 128B-contiguous global writes
#pragma unroll 1
    for (int p = 0; p < 4; p++) {
        const int row = (tid >> 3) + p * 16;
        const int ct  = (tid & 7) * 4;
        const float* er = eps + row * EPSS;
        const size_t gbase = (size_t)(m0 + row) * HID_ + n0 + ct;
        const float4 cv = *reinterpret_cast<const float4*>(cprev + gbase);
        float4 hn, cn;
#pragma unroll
        for (int j = 0; j < 4; j++) {
            const int cc = ct + j;
            const float gi = er[cc]      + eps[BIAS_OFF + cc];
            const float gf = er[32 + cc] + eps[BIAS_OFF + 32 + cc];
            const float gc = er[64 + cc] + eps[BIAS_OFF + 64 + cc];
            const float go = er[96 + cc] + eps[BIAS_OFF + 96 + cc];
            const float ig = sigmoid_f(gi);
            const float fg = sigmoid_f(gf);
            const float cg = tanhf(gc);
            const float og = sigmoid_f(go);
            const float cpv = (j == 0) ? cv.x : (j == 1) ? cv.y : (j == 2) ? cv.z : cv.w;
            const float cnv = fg * cpv + ig * cg;
            const float hnv = og * tanhf(cnv);
            if (j == 0) { hn.x = hnv; cn.x = cnv; }
            else if (j == 1) { hn.y = hnv; cn.y = cnv; }
            else if (j == 2) { hn.z = hnv; cn.z = cnv; }
            else { hn.w = hnv; cn.w = cnv; }
        }
        *reinterpret_cast<float4*>(out + gbase)      = hn;
        *reinterpret_cast<float4*>(out + BH + gbase) = cn;
    }
}

// ---------------- launch ----------------
extern "C" void kernel_launch(void* const* d_in, const int* in_sizes, int n_in,
                              void* d_out, int out_size)
{
    (void)in_sizes; (void)n_in; (void)out_size;
    const float* x    = (const float*)d_in[0];
    const float* h    = (const float*)d_in[1];
    const float* c    = (const float*)d_in[2];
    const float* w_ih = (const float*)d_in[3];
    const float* w_hh = (const float*)d_in[4];
    const float* b_ih = (const float*)d_in[5];
    const float* b_hh = (const float*)d_in[6];
    float* out = (float*)d_out;

    // 1) merged conversion: z=0 -> A f16, z=1..4 -> weight transpose f16
    conv_kernel<<<dim3(64, 128, 5), 256>>>(x, h, w_ih, w_hh);

    // 2) fused f16 GEMM + LSTM epilogue, 128-thread CTAs, 4 CTAs/SM
    //    (m-fastest grid for B-panel L2 reuse)
    cudaFuncSetAttribute(lstm_fused_kernel,
                         cudaFuncAttributeMaxDynamicSharedMemorySize, SMEM_TOTAL);
    dim3 gg(BATCH_ / BM, HID_ / 32);   // (64, 64)
    lstm_fused_kernel<<<gg, 128, SMEM_TOTAL>>>(c, b_ih, b_hh, out);
}